// round 13
// baseline (speedup 1.0000x reference)
#include <cuda_runtime.h>
#include <math.h>
#include <stdint.h>

#define Bn 8
#define An 100000
#define Kn 80
#define Mn 32
#define F4_TOTAL 2000000                 /* float4 per image */
#define TPB 256

/* ---- assign geometry: 512 anchors per block, 2 per thread (R11) ---- */
#define APB 512
#define AGX2 ((An + APB - 1) / APB)      /* 196 */

/* ---- focal geometry: EXACT R11 config (measured 46.9 us, 70% DRAM) ---- */
#define CHUNK_F4   1024
#define CHUNK_BYTES 16384
#define NST 4                            /* 64 KB dynamic smem */
#define CH_IMG 1954                      /* 1953 full + 1 tail chunk */
#define TAIL_F4 128
#define GXI 55                           /* 440 blocks = 3/SM */
#define NBLKF (GXI * Bn)

typedef unsigned long long u64;

// ---------------- device scratch --------------------------------------------
__device__ float g_pcls[NBLKF];
__device__ float g_preg[Bn * AGX2];
__device__ float g_pnp [Bn * AGX2];
__device__ float g_pcor[Bn * AGX2];

// ---------------- fast intrinsics -------------------------------------------
__device__ __forceinline__ float fast_ex2(float x) { float r; asm("ex2.approx.f32 %0, %1;" : "=f"(r) : "f"(x)); return r; }
__device__ __forceinline__ float fast_lg2(float x) { float r; asm("lg2.approx.f32 %0, %1;" : "=f"(r) : "f"(x)); return r; }
__device__ __forceinline__ float fast_rcp(float x) { float r; asm("rcp.approx.f32 %0, %1;" : "=f"(r) : "f"(x)); return r; }

// ---------------- packed f32x2 helpers --------------------------------------
__device__ __forceinline__ u64 fma2(u64 a, u64 b, u64 c) {
    u64 d; asm("fma.rn.f32x2 %0, %1, %2, %3;" : "=l"(d) : "l"(a), "l"(b), "l"(c)); return d;
}
__device__ __forceinline__ u64 add2(u64 a, u64 b) {
    u64 d; asm("add.rn.f32x2 %0, %1, %2;" : "=l"(d) : "l"(a), "l"(b)); return d;
}
__device__ __forceinline__ void upkf(u64 v, float& lo, float& hi) {
    unsigned a, b; asm("mov.b64 {%0, %1}, %2;" : "=r"(a), "=r"(b) : "l"(v));
    lo = __uint_as_float(a); hi = __uint_as_float(b);
}
__device__ __forceinline__ u64 pk2c(float c) {
    unsigned u = __float_as_uint(c); return ((u64)u << 32) | (u64)u;
}

// ---- degree-6 Taylor of f1(x)=0.25*(1-sigmoid(x))^2*softplus(-x) at x0=0.5
// (validated rounds 4-12 end-to-end at rel_err ~1.36e-6)
#define CB0  0.01689337f
#define CB1 -0.03448426f
#define CB2  0.03005625f
#define CB3 -0.01298390f
#define CB4  0.00148816f
#define CB5  0.00118042f
#define CB6 -0.00048818f
#define C0_PER_IMAGE (CB0 * 8000000.0f)

__device__ __forceinline__ float poly_x(float x) {
    float s = x - 0.5f;
    float p = fmaf(CB6, s, CB5);
    p = fmaf(p, s, CB4); p = fmaf(p, s, CB3);
    p = fmaf(p, s, CB2); p = fmaf(p, s, CB1);
    return fmaf(p, s, CB0);
}
__device__ __forceinline__ float f1_precise(float xc) {
    float e = fast_ex2(-1.44269504f * xc);
    float q = 1.0f + e;
    float u = fast_rcp(q);
    float omp = e * u;
    return 0.17328680f * (omp * omp) * fast_lg2(q);
}
__device__ __forceinline__ float f2_precise(float xc) {
    float e = fast_ex2(-1.44269504f * xc);
    float q = 1.0f + e;
    float u = fast_rcp(q);
    float sp = 0.69314718f * fast_lg2(q);
    return 0.75f * (u * u) * (xc + sp);
}

struct PK { u64 h, c6, c5, c4, c3, c2, c1; };
__device__ __forceinline__ void pair_acc(u64& acc, u64 x2, const PK& K) {
    u64 s = add2(x2, K.h);
    u64 p = fma2(K.c6, s, K.c5);
    p = fma2(p, s, K.c4);
    p = fma2(p, s, K.c3);
    p = fma2(p, s, K.c2);
    p = fma2(p, s, K.c1);
    acc = fma2(p, s, acc);
}

__device__ __forceinline__ void mb_wait_acq(unsigned mb, unsigned ph) {
    asm volatile(
        "{\n\t.reg .pred P1;\n\t"
        "WLP_%=:\n\t"
        "mbarrier.try_wait.parity.acquire.cta.shared::cta.b64 P1, [%0], %1, 0x989680;\n\t"
        "@P1 bra.uni WDN_%=;\n\t"
        "bra.uni WLP_%=;\n\t"
        "WDN_%=:\n\t}"
        :: "r"(mb), "r"(ph) : "memory");
}

// ============ kernel A: assign (byte-identical logic to R11) ================
__global__ void __launch_bounds__(TPB) assign_kernel(
    const float* __restrict__ cls,
    const float* __restrict__ regs,
    const float* __restrict__ anc,
    const float* __restrict__ ann)
{
    __shared__ float4 vbox[Mn];
    __shared__ float  vlab[Mn];
    __shared__ int    s_V;
    __shared__ int    s_pa[APB];
    __shared__ int    s_pcode[APB];
    __shared__ int    s_pcnt;
    __shared__ float  s_regsum;
    __shared__ float  wC[TPB / 32];

    const int b = blockIdx.y;
    const int t = threadIdx.x;

    if (t == 0) { s_pcnt = 0; s_regsum = 0.f; }
    if (t < 32) {
        const float* a5 = ann + ((size_t)b * Mn + t) * 5;
        float x1 = a5[0], y1 = a5[1], x2 = a5[2], y2 = a5[3], lb = a5[4];
        bool val = (lb != -1.0f);
        unsigned m = __ballot_sync(0xffffffffu, val);
        int pos = __popc(m & ((1u << t) - 1));
        int V = __popc(m);
        if (val) {
            vbox[pos] = make_float4(x1, y1, x2, y2);
            vlab[pos] = lb;
        }
        if (t >= V) {
            vbox[t] = make_float4(1e18f, 1e18f, 1e18f, 1e18f);
            vlab[t] = 0.f;
        }
        if (t == 0) s_V = V;
    }
    __syncthreads();
    const int V = s_V;

    const int base = blockIdx.x * APB;
    const int a0 = base + t;
    const int a1 = base + t + TPB;
    const bool ok0 = (a0 < An), ok1 = (a1 < An);
    float4 A0 = ok0 ? *(const float4*)(anc + (size_t)a0 * 4)
                    : make_float4(-1e18f, -1e18f, -1e18f, -1e18f);
    float4 A1 = ok1 ? *(const float4*)(anc + (size_t)a1 * 4)
                    : make_float4(-1e18f, -1e18f, -1e18f, -1e18f);
    const float areaA0 = (A0.z - A0.x) * (A0.w - A0.y);
    const float areaA1 = (A1.z - A1.x) * (A1.w - A1.y);

    bool p0 = false, p1 = false;
    #pragma unroll
    for (int m = 0; m < Mn; m++) {
        float4 bb = vbox[m];
        float barea = (bb.z - bb.x) * (bb.w - bb.y);
        {
            float iw = fmaxf(fminf(A0.z, bb.z) - fmaxf(A0.x, bb.x), 0.f);
            float ih = fmaxf(fminf(A0.w, bb.w) - fmaxf(A0.y, bb.y), 0.f);
            float inter = iw * ih;
            float ua = fmaxf(areaA0 + barea - inter, 1e-8f);
            p0 = p0 || (inter + inter >= ua);
        }
        {
            float iw = fmaxf(fminf(A1.z, bb.z) - fmaxf(A1.x, bb.x), 0.f);
            float ih = fmaxf(fminf(A1.w, bb.w) - fmaxf(A1.y, bb.y), 0.f);
            float inter = iw * ih;
            float ua = fmaxf(areaA1 + barea - inter, 1e-8f);
            p1 = p1 || (inter + inter >= ua);
        }
    }
    if (p0 && ok0) { int i = atomicAdd(&s_pcnt, 1); s_pa[i] = a0; }
    if (p1 && ok1) { int i = atomicAdd(&s_pcnt, 1); s_pa[i] = a1; }
    __syncthreads();
    const int P = s_pcnt;

    for (int i = t; i < P; i += TPB) {
        int ap = s_pa[i];
        float4 av = *(const float4*)(anc + (size_t)ap * 4);
        float px1 = av.x, py1 = av.y, px2 = av.z, py2 = av.w;
        float areaP = (px2 - px1) * (py2 - py1);
        float binter = 0.f, bua = 1.f; int bi = 0;
        for (int m = 0; m < V; m++) {
            float4 bb = vbox[m];
            float barea = (bb.z - bb.x) * (bb.w - bb.y);
            float iw = fmaxf(fminf(px2, bb.z) - fmaxf(px1, bb.x), 0.f);
            float ih = fmaxf(fminf(py2, bb.w) - fmaxf(py1, bb.y), 0.f);
            float inter = iw * ih;
            float ua = fmaxf(areaP + barea - inter, 1e-8f);
            if (m == 0) { binter = inter; bua = ua; }
            else if (inter * bua > binter * ua) { binter = inter; bua = ua; bi = m; }
        }
        s_pcode[i] = (int)vlab[bi];

        float aw = px2 - px1, ah = py2 - py1;
        float acx = px1 + 0.5f * aw, acy = py1 + 0.5f * ah;
        float4 gb = vbox[bi];
        float gw = gb.z - gb.x, gh = gb.w - gb.y;
        float gcx = gb.x + 0.5f * gw, gcy = gb.y + 0.5f * gh;
        gw = fmaxf(gw, 1.0f); gh = fmaxf(gh, 1.0f);
        float tt0 = ((gcx - acx) / aw) / 0.1f;
        float tt1 = ((gcy - acy) / ah) / 0.1f;
        float tt2 = __logf(gw / aw) / 0.2f;
        float tt3 = __logf(gh / ah) / 0.2f;
        float4 rv = *(const float4*)(regs + ((size_t)b * An + ap) * 4);
        float d0 = fabsf(tt0 - rv.x), d1 = fabsf(tt1 - rv.y);
        float d2 = fabsf(tt2 - rv.z), d3 = fabsf(tt3 - rv.w);
        float srl = 0.f;
        srl += (d0 <= (float)(1.0/9.0)) ? 4.5f*d0*d0 : d0 - (float)(0.5/9.0);
        srl += (d1 <= (float)(1.0/9.0)) ? 4.5f*d1*d1 : d1 - (float)(0.5/9.0);
        srl += (d2 <= (float)(1.0/9.0)) ? 4.5f*d2*d2 : d2 - (float)(0.5/9.0);
        srl += (d3 <= (float)(1.0/9.0)) ? 4.5f*d3*d3 : d3 - (float)(0.5/9.0);
        atomicAdd(&s_regsum, srl);
    }
    __syncthreads();

    float corr = 0.f;
    const int total = P * 20;
    for (int w = t; w < total; w += TPB) {
        int i = w / 20, j = w - i * 20;
        int ap = s_pa[i];
        int code = s_pcode[i];
        float4 c = *((const float4*)(cls + ((size_t)b * An + ap) * Kn) + j);
        int k0 = j * 4;
        #pragma unroll
        for (int e = 0; e < 4; e++) {
            float x = (e == 0) ? c.x : (e == 1) ? c.y : (e == 2) ? c.z : c.w;
            float xc = fminf(fmaxf(x, 1e-4f), 0.9999f);
            float truth = (k0 + e == code) ? f1_precise(xc) : f2_precise(xc);
            corr += truth - poly_x(x);
        }
    }
    #pragma unroll
    for (int o = 16; o > 0; o >>= 1) corr += __shfl_down_sync(0xffffffffu, corr, o);
    if ((t & 31) == 0) wC[t >> 5] = corr;
    __syncthreads();
    if (t == 0) {
        float C = 0.f;
        #pragma unroll
        for (int w2 = 0; w2 < TPB / 32; w2++) C += wC[w2];
        int bid = b * AGX2 + blockIdx.x;
        g_pnp [bid] = (float)P;
        g_preg[bid] = s_regsum;
        g_pcor[bid] = C;
    }
}

// ============ kernel B: R11 TMA streaming poly (partials only) ==============
__global__ void __launch_bounds__(TPB) focal_kernel(const float* __restrict__ cls)
{
    extern __shared__ char dynsmem[];            // NST * CHUNK_BYTES = 64 KB
    __shared__ u64 mbar[NST];
    __shared__ float wsum[TPB / 32];

    const int b  = blockIdx.y;
    const int bx = blockIdx.x;
    const int t  = threadIdx.x;

    const unsigned smem_base = (unsigned)__cvta_generic_to_shared(dynsmem);
    const unsigned mbar_base = (unsigned)__cvta_generic_to_shared(&mbar[0]);
    const char* gbase = (const char*)cls + (size_t)b * F4_TOTAL * 16;

    if (t == 0) {
        #pragma unroll
        for (int s = 0; s < NST; s++)
            asm volatile("mbarrier.init.shared.b64 [%0], %1;"
                         :: "r"(mbar_base + s * 8), "r"(1u) : "memory");
    }
    __syncthreads();

    const int n = (CH_IMG - bx + GXI - 1) / GXI;

    auto issue = [&](int i) {
        int c = bx + i * GXI;
        unsigned cnt = (c == CH_IMG - 1) ? TAIL_F4 : CHUNK_F4;
        unsigned bytes = cnt * 16u;
        int st = i & (NST - 1);
        unsigned mb = mbar_base + st * 8;
        asm volatile("mbarrier.arrive.expect_tx.shared.b64 _, [%0], %1;"
                     :: "r"(mb), "r"(bytes) : "memory");
        asm volatile("cp.async.bulk.shared::cta.global.mbarrier::complete_tx::bytes [%0], [%1], %2, [%3];"
                     :: "r"(smem_base + st * CHUNK_BYTES),
                        "l"(gbase + (size_t)c * CHUNK_BYTES),
                        "r"(bytes), "r"(mb) : "memory");
    };

    if (t == 0) {
        for (int i = 0; i < n && i < NST; i++) issue(i);
    }

    PK K;
    K.h  = pk2c(-0.5f);
    K.c6 = pk2c(CB6); K.c5 = pk2c(CB5); K.c4 = pk2c(CB4);
    K.c3 = pk2c(CB3); K.c2 = pk2c(CB2); K.c1 = pk2c(CB1);

    u64 accA = 0ull, accB = 0ull;

    for (int i = 0; i < n; i++) {
        int st = i & (NST - 1);
        unsigned ph = (unsigned)((i >> 2) & 1);
        mb_wait_acq(mbar_base + st * 8, ph);

        int c = bx + i * GXI;
        const ulonglong2* sp = (const ulonglong2*)(dynsmem + st * CHUNK_BYTES);
        if (c != CH_IMG - 1) {
            ulonglong2 v0 = sp[t];
            ulonglong2 v1 = sp[t + 256];
            ulonglong2 v2 = sp[t + 512];
            ulonglong2 v3 = sp[t + 768];
            pair_acc(accA, v0.x, K); pair_acc(accB, v0.y, K);
            pair_acc(accA, v1.x, K); pair_acc(accB, v1.y, K);
            pair_acc(accA, v2.x, K); pair_acc(accB, v2.y, K);
            pair_acc(accA, v3.x, K); pair_acc(accB, v3.y, K);
        } else {
            if (t < TAIL_F4) {
                ulonglong2 v = sp[t];
                pair_acc(accA, v.x, K); pair_acc(accB, v.y, K);
            }
        }
        __syncthreads();
        if (t == 0 && i + NST < n) issue(i + NST);
    }

    float la, ha, lb2, hb2;
    upkf(accA, la, ha); upkf(accB, lb2, hb2);
    float acc = (la + ha) + (lb2 + hb2);

    #pragma unroll
    for (int o = 16; o > 0; o >>= 1) acc += __shfl_down_sync(0xffffffffu, acc, o);
    if ((t & 31) == 0) wsum[t >> 5] = acc;
    __syncthreads();
    if (t == 0) {
        float v = 0.f;
        #pragma unroll
        for (int w = 0; w < TPB / 32; w++) v += wsum[w];
        g_pcls[b * GXI + bx] = v;
    }
}

// ============ kernel C: finalize (runs after join) ==========================
__global__ void __launch_bounds__(TPB) final_kernel(
    const float* __restrict__ ann, float* __restrict__ out, int out_size)
{
    __shared__ float s_c[Bn], s_r[Bn];
    const int t = threadIdx.x;
    const int w = t >> 5;                // warp w handles image w
    const int lane = t & 31;

    float C = 0.f, R = 0.f, N = 0.f;
    for (int j = lane; j < GXI; j += 32) C += g_pcls[w * GXI + j];
    for (int j = lane; j < AGX2; j += 32) {
        C += g_pcor[w * AGX2 + j];
        R += g_preg[w * AGX2 + j];
        N += g_pnp [w * AGX2 + j];
    }
    #pragma unroll
    for (int o = 16; o > 0; o >>= 1) {
        C += __shfl_down_sync(0xffffffffu, C, o);
        R += __shfl_down_sync(0xffffffffu, R, o);
        N += __shfl_down_sync(0xffffffffu, N, o);
    }
    float lab = ann[((size_t)w * Mn + lane) * 5 + 4];
    unsigned hasmask = __ballot_sync(0xffffffffu, lab != -1.0f);
    if (lane == 0) {
        float Ct = C + C0_PER_IMAGE;
        float clsv = Ct / fmaxf(N, 0.01f);
        float regv = (N > 0.f) ? (R / fmaxf(N * 4.0f, 1.0f)) : 0.f;
        if (hasmask == 0u) { clsv = 0.f; regv = 0.f; }
        s_c[w] = clsv; s_r[w] = regv;
    }
    __syncthreads();
    if (t == 0) {
        float sc = 0.f, sr = 0.f;
        #pragma unroll
        for (int i = 0; i < Bn; i++) { sc += s_c[i]; sr += s_r[i]; }
        out[0] = sc * (1.0f / (float)Bn);
        if (out_size > 1) out[1] = sr * (1.0f / (float)Bn);
    }
}

// ---------------- launch: graph-parallel fork/join ---------------------------
extern "C" void kernel_launch(void* const* d_in, const int* in_sizes, int n_in,
                              void* d_out, int out_size) {
    const float *cls = nullptr, *reg = nullptr, *anc = nullptr, *ann = nullptr;
    for (int i = 0; i < n_in; i++) {
        long long sz = in_sizes[i];
        if      (sz == (long long)Bn * An * Kn) cls = (const float*)d_in[i];
        else if (sz == (long long)Bn * An * 4)  reg = (const float*)d_in[i];
        else if (sz == (long long)An * 4)       anc = (const float*)d_in[i];
        else if (sz == (long long)Bn * Mn * 5)  ann = (const float*)d_in[i];
    }

    // Created once on the FIRST call (the uncaptured correctness run).
    // No device-memory allocation: streams/events only.
    static cudaStream_t s1 = nullptr;
    static cudaEvent_t e_fork = nullptr, e_join = nullptr;
    if (s1 == nullptr) {
        cudaFuncSetAttribute(focal_kernel,
            cudaFuncAttributeMaxDynamicSharedMemorySize, NST * CHUNK_BYTES);
        cudaStreamCreateWithFlags(&s1, cudaStreamNonBlocking);
        cudaEventCreateWithFlags(&e_fork, cudaEventDisableTiming);
        cudaEventCreateWithFlags(&e_join, cudaEventDisableTiming);
    }

    // fork: bring s1 into the capture as a parallel branch
    cudaEventRecord(e_fork, 0);
    cudaStreamWaitEvent(s1, e_fork, 0);

    dim3 ga(AGX2, Bn);
    assign_kernel<<<ga, TPB, 0, s1>>>(cls, reg, anc, ann);

    dim3 gf(GXI, Bn);
    focal_kernel<<<gf, TPB, NST * CHUNK_BYTES>>>(cls);

    // join: finalize depends on both branches
    cudaEventRecord(e_join, s1);
    cudaStreamWaitEvent(0, e_join, 0);

    final_kernel<<<1, TPB>>>(ann, (float*)d_out, out_size);
}

// round 14
// speedup vs baseline: 1.0609x; 1.0609x over previous
#include <cuda_runtime.h>
#include <math.h>
#include <stdint.h>

#define Bn 8
#define An 100000
#define Kn 80
#define Mn 32
#define F4_TOTAL 2000000                 /* float4 per image */
#define TPB 256

/* ---- assign geometry: 512 anchors per block, 2 per thread (R11) ---- */
#define APB 512
#define AGX2 ((An + APB - 1) / APB)      /* 196 */

/* ---- focal geometry: EXACT R11 config (measured 46.9 us, 70% DRAM) ---- */
#define CHUNK_F4   1024
#define CHUNK_BYTES 16384
#define NST 4                            /* 64 KB dynamic smem */
#define CH_IMG 1954                      /* 1953 full + 1 tail chunk */
#define TAIL_F4 128
#define GXI 55                           /* 440 blocks = 3/SM */
#define NBLKF (GXI * Bn)

typedef unsigned long long u64;

// ---------------- device scratch --------------------------------------------
__device__ float g_pcls[NBLKF];
__device__ float g_preg[Bn * AGX2];
__device__ float g_pnp [Bn * AGX2];
__device__ float g_pcor[Bn * AGX2];

// ---------------- fast intrinsics -------------------------------------------
__device__ __forceinline__ float fast_ex2(float x) { float r; asm("ex2.approx.f32 %0, %1;" : "=f"(r) : "f"(x)); return r; }
__device__ __forceinline__ float fast_lg2(float x) { float r; asm("lg2.approx.f32 %0, %1;" : "=f"(r) : "f"(x)); return r; }
__device__ __forceinline__ float fast_rcp(float x) { float r; asm("rcp.approx.f32 %0, %1;" : "=f"(r) : "f"(x)); return r; }

// ---------------- packed f32x2 helpers --------------------------------------
__device__ __forceinline__ u64 fma2(u64 a, u64 b, u64 c) {
    u64 d; asm("fma.rn.f32x2 %0, %1, %2, %3;" : "=l"(d) : "l"(a), "l"(b), "l"(c)); return d;
}
__device__ __forceinline__ u64 add2(u64 a, u64 b) {
    u64 d; asm("add.rn.f32x2 %0, %1, %2;" : "=l"(d) : "l"(a), "l"(b)); return d;
}
__device__ __forceinline__ void upkf(u64 v, float& lo, float& hi) {
    unsigned a, b; asm("mov.b64 {%0, %1}, %2;" : "=r"(a), "=r"(b) : "l"(v));
    lo = __uint_as_float(a); hi = __uint_as_float(b);
}
__device__ __forceinline__ u64 pk2c(float c) {
    unsigned u = __float_as_uint(c); return ((u64)u << 32) | (u64)u;
}

// ---- degree-6 Taylor of f1(x)=0.25*(1-sigmoid(x))^2*softplus(-x) at x0=0.5
// (validated rounds 4-13 end-to-end at rel_err ~1.36e-6)
#define CB0  0.01689337f
#define CB1 -0.03448426f
#define CB2  0.03005625f
#define CB3 -0.01298390f
#define CB4  0.00148816f
#define CB5  0.00118042f
#define CB6 -0.00048818f
#define C0_PER_IMAGE (CB0 * 8000000.0f)

__device__ __forceinline__ float poly_x(float x) {
    float s = x - 0.5f;
    float p = fmaf(CB6, s, CB5);
    p = fmaf(p, s, CB4); p = fmaf(p, s, CB3);
    p = fmaf(p, s, CB2); p = fmaf(p, s, CB1);
    return fmaf(p, s, CB0);
}
__device__ __forceinline__ float f1_precise(float xc) {
    float e = fast_ex2(-1.44269504f * xc);
    float q = 1.0f + e;
    float u = fast_rcp(q);
    float omp = e * u;
    return 0.17328680f * (omp * omp) * fast_lg2(q);
}
__device__ __forceinline__ float f2_precise(float xc) {
    float e = fast_ex2(-1.44269504f * xc);
    float q = 1.0f + e;
    float u = fast_rcp(q);
    float sp = 0.69314718f * fast_lg2(q);
    return 0.75f * (u * u) * (xc + sp);
}

struct PK { u64 h, c6, c5, c4, c3, c2, c1; };
__device__ __forceinline__ void pair_acc(u64& acc, u64 x2, const PK& K) {
    u64 s = add2(x2, K.h);
    u64 p = fma2(K.c6, s, K.c5);
    p = fma2(p, s, K.c4);
    p = fma2(p, s, K.c3);
    p = fma2(p, s, K.c2);
    p = fma2(p, s, K.c1);
    acc = fma2(p, s, acc);
}

__device__ __forceinline__ void mb_wait_acq(unsigned mb, unsigned ph) {
    asm volatile(
        "{\n\t.reg .pred P1;\n\t"
        "WLP_%=:\n\t"
        "mbarrier.try_wait.parity.acquire.cta.shared::cta.b64 P1, [%0], %1, 0x989680;\n\t"
        "@P1 bra.uni WDN_%=;\n\t"
        "bra.uni WLP_%=;\n\t"
        "WDN_%=:\n\t}"
        :: "r"(mb), "r"(ph) : "memory");
}

// ============ kernel A: assign (byte-identical logic to R11/R13) ============
__global__ void __launch_bounds__(TPB) assign_kernel(
    const float* __restrict__ cls,
    const float* __restrict__ regs,
    const float* __restrict__ anc,
    const float* __restrict__ ann)
{
    __shared__ float4 vbox[Mn];
    __shared__ float  vlab[Mn];
    __shared__ int    s_V;
    __shared__ int    s_pa[APB];
    __shared__ int    s_pcode[APB];
    __shared__ int    s_pcnt;
    __shared__ float  s_regsum;
    __shared__ float  wC[TPB / 32];

    const int b = blockIdx.y;
    const int t = threadIdx.x;

    if (t == 0) { s_pcnt = 0; s_regsum = 0.f; }
    if (t < 32) {
        const float* a5 = ann + ((size_t)b * Mn + t) * 5;
        float x1 = a5[0], y1 = a5[1], x2 = a5[2], y2 = a5[3], lb = a5[4];
        bool val = (lb != -1.0f);
        unsigned m = __ballot_sync(0xffffffffu, val);
        int pos = __popc(m & ((1u << t) - 1));
        int V = __popc(m);
        if (val) {
            vbox[pos] = make_float4(x1, y1, x2, y2);
            vlab[pos] = lb;
        }
        if (t >= V) {
            vbox[t] = make_float4(1e18f, 1e18f, 1e18f, 1e18f);
            vlab[t] = 0.f;
        }
        if (t == 0) s_V = V;
    }
    __syncthreads();
    const int V = s_V;

    const int base = blockIdx.x * APB;
    const int a0 = base + t;
    const int a1 = base + t + TPB;
    const bool ok0 = (a0 < An), ok1 = (a1 < An);
    float4 A0 = ok0 ? *(const float4*)(anc + (size_t)a0 * 4)
                    : make_float4(-1e18f, -1e18f, -1e18f, -1e18f);
    float4 A1 = ok1 ? *(const float4*)(anc + (size_t)a1 * 4)
                    : make_float4(-1e18f, -1e18f, -1e18f, -1e18f);
    const float areaA0 = (A0.z - A0.x) * (A0.w - A0.y);
    const float areaA1 = (A1.z - A1.x) * (A1.w - A1.y);

    bool p0 = false, p1 = false;
    #pragma unroll
    for (int m = 0; m < Mn; m++) {
        float4 bb = vbox[m];
        float barea = (bb.z - bb.x) * (bb.w - bb.y);
        {
            float iw = fmaxf(fminf(A0.z, bb.z) - fmaxf(A0.x, bb.x), 0.f);
            float ih = fmaxf(fminf(A0.w, bb.w) - fmaxf(A0.y, bb.y), 0.f);
            float inter = iw * ih;
            float ua = fmaxf(areaA0 + barea - inter, 1e-8f);
            p0 = p0 || (inter + inter >= ua);
        }
        {
            float iw = fmaxf(fminf(A1.z, bb.z) - fmaxf(A1.x, bb.x), 0.f);
            float ih = fmaxf(fminf(A1.w, bb.w) - fmaxf(A1.y, bb.y), 0.f);
            float inter = iw * ih;
            float ua = fmaxf(areaA1 + barea - inter, 1e-8f);
            p1 = p1 || (inter + inter >= ua);
        }
    }
    if (p0 && ok0) { int i = atomicAdd(&s_pcnt, 1); s_pa[i] = a0; }
    if (p1 && ok1) { int i = atomicAdd(&s_pcnt, 1); s_pa[i] = a1; }
    __syncthreads();
    const int P = s_pcnt;

    for (int i = t; i < P; i += TPB) {
        int ap = s_pa[i];
        float4 av = *(const float4*)(anc + (size_t)ap * 4);
        float px1 = av.x, py1 = av.y, px2 = av.z, py2 = av.w;
        float areaP = (px2 - px1) * (py2 - py1);
        float binter = 0.f, bua = 1.f; int bi = 0;
        for (int m = 0; m < V; m++) {
            float4 bb = vbox[m];
            float barea = (bb.z - bb.x) * (bb.w - bb.y);
            float iw = fmaxf(fminf(px2, bb.z) - fmaxf(px1, bb.x), 0.f);
            float ih = fmaxf(fminf(py2, bb.w) - fmaxf(py1, bb.y), 0.f);
            float inter = iw * ih;
            float ua = fmaxf(areaP + barea - inter, 1e-8f);
            if (m == 0) { binter = inter; bua = ua; }
            else if (inter * bua > binter * ua) { binter = inter; bua = ua; bi = m; }
        }
        s_pcode[i] = (int)vlab[bi];

        float aw = px2 - px1, ah = py2 - py1;
        float acx = px1 + 0.5f * aw, acy = py1 + 0.5f * ah;
        float4 gb = vbox[bi];
        float gw = gb.z - gb.x, gh = gb.w - gb.y;
        float gcx = gb.x + 0.5f * gw, gcy = gb.y + 0.5f * gh;
        gw = fmaxf(gw, 1.0f); gh = fmaxf(gh, 1.0f);
        float tt0 = ((gcx - acx) / aw) / 0.1f;
        float tt1 = ((gcy - acy) / ah) / 0.1f;
        float tt2 = __logf(gw / aw) / 0.2f;
        float tt3 = __logf(gh / ah) / 0.2f;
        float4 rv = *(const float4*)(regs + ((size_t)b * An + ap) * 4);
        float d0 = fabsf(tt0 - rv.x), d1 = fabsf(tt1 - rv.y);
        float d2 = fabsf(tt2 - rv.z), d3 = fabsf(tt3 - rv.w);
        float srl = 0.f;
        srl += (d0 <= (float)(1.0/9.0)) ? 4.5f*d0*d0 : d0 - (float)(0.5/9.0);
        srl += (d1 <= (float)(1.0/9.0)) ? 4.5f*d1*d1 : d1 - (float)(0.5/9.0);
        srl += (d2 <= (float)(1.0/9.0)) ? 4.5f*d2*d2 : d2 - (float)(0.5/9.0);
        srl += (d3 <= (float)(1.0/9.0)) ? 4.5f*d3*d3 : d3 - (float)(0.5/9.0);
        atomicAdd(&s_regsum, srl);
    }
    __syncthreads();

    float corr = 0.f;
    const int total = P * 20;
    for (int w = t; w < total; w += TPB) {
        int i = w / 20, j = w - i * 20;
        int ap = s_pa[i];
        int code = s_pcode[i];
        float4 c = *((const float4*)(cls + ((size_t)b * An + ap) * Kn) + j);
        int k0 = j * 4;
        #pragma unroll
        for (int e = 0; e < 4; e++) {
            float x = (e == 0) ? c.x : (e == 1) ? c.y : (e == 2) ? c.z : c.w;
            float xc = fminf(fmaxf(x, 1e-4f), 0.9999f);
            float truth = (k0 + e == code) ? f1_precise(xc) : f2_precise(xc);
            corr += truth - poly_x(x);
        }
    }
    #pragma unroll
    for (int o = 16; o > 0; o >>= 1) corr += __shfl_down_sync(0xffffffffu, corr, o);
    if ((t & 31) == 0) wC[t >> 5] = corr;
    __syncthreads();
    if (t == 0) {
        float C = 0.f;
        #pragma unroll
        for (int w2 = 0; w2 < TPB / 32; w2++) C += wC[w2];
        int bid = b * AGX2 + blockIdx.x;
        g_pnp [bid] = (float)P;
        g_preg[bid] = s_regsum;
        g_pcor[bid] = C;
    }
}

// ============ kernel B: R11 TMA streaming poly (partials only) ==============
__global__ void __launch_bounds__(TPB) focal_kernel(const float* __restrict__ cls)
{
    extern __shared__ char dynsmem[];            // NST * CHUNK_BYTES = 64 KB
    __shared__ u64 mbar[NST];
    __shared__ float wsum[TPB / 32];

    const int b  = blockIdx.y;
    const int bx = blockIdx.x;
    const int t  = threadIdx.x;

    const unsigned smem_base = (unsigned)__cvta_generic_to_shared(dynsmem);
    const unsigned mbar_base = (unsigned)__cvta_generic_to_shared(&mbar[0]);
    const char* gbase = (const char*)cls + (size_t)b * F4_TOTAL * 16;

    if (t == 0) {
        #pragma unroll
        for (int s = 0; s < NST; s++)
            asm volatile("mbarrier.init.shared.b64 [%0], %1;"
                         :: "r"(mbar_base + s * 8), "r"(1u) : "memory");
    }
    __syncthreads();

    const int n = (CH_IMG - bx + GXI - 1) / GXI;

    auto issue = [&](int i) {
        int c = bx + i * GXI;
        unsigned cnt = (c == CH_IMG - 1) ? TAIL_F4 : CHUNK_F4;
        unsigned bytes = cnt * 16u;
        int st = i & (NST - 1);
        unsigned mb = mbar_base + st * 8;
        asm volatile("mbarrier.arrive.expect_tx.shared.b64 _, [%0], %1;"
                     :: "r"(mb), "r"(bytes) : "memory");
        asm volatile("cp.async.bulk.shared::cta.global.mbarrier::complete_tx::bytes [%0], [%1], %2, [%3];"
                     :: "r"(smem_base + st * CHUNK_BYTES),
                        "l"(gbase + (size_t)c * CHUNK_BYTES),
                        "r"(bytes), "r"(mb) : "memory");
    };

    if (t == 0) {
        for (int i = 0; i < n && i < NST; i++) issue(i);
    }

    PK K;
    K.h  = pk2c(-0.5f);
    K.c6 = pk2c(CB6); K.c5 = pk2c(CB5); K.c4 = pk2c(CB4);
    K.c3 = pk2c(CB3); K.c2 = pk2c(CB2); K.c1 = pk2c(CB1);

    u64 accA = 0ull, accB = 0ull;

    for (int i = 0; i < n; i++) {
        int st = i & (NST - 1);
        unsigned ph = (unsigned)((i >> 2) & 1);
        mb_wait_acq(mbar_base + st * 8, ph);

        int c = bx + i * GXI;
        const ulonglong2* sp = (const ulonglong2*)(dynsmem + st * CHUNK_BYTES);
        if (c != CH_IMG - 1) {
            ulonglong2 v0 = sp[t];
            ulonglong2 v1 = sp[t + 256];
            ulonglong2 v2 = sp[t + 512];
            ulonglong2 v3 = sp[t + 768];
            pair_acc(accA, v0.x, K); pair_acc(accB, v0.y, K);
            pair_acc(accA, v1.x, K); pair_acc(accB, v1.y, K);
            pair_acc(accA, v2.x, K); pair_acc(accB, v2.y, K);
            pair_acc(accA, v3.x, K); pair_acc(accB, v3.y, K);
        } else {
            if (t < TAIL_F4) {
                ulonglong2 v = sp[t];
                pair_acc(accA, v.x, K); pair_acc(accB, v.y, K);
            }
        }
        __syncthreads();
        if (t == 0 && i + NST < n) issue(i + NST);
    }

    float la, ha, lb2, hb2;
    upkf(accA, la, ha); upkf(accB, lb2, hb2);
    float acc = (la + ha) + (lb2 + hb2);

    #pragma unroll
    for (int o = 16; o > 0; o >>= 1) acc += __shfl_down_sync(0xffffffffu, acc, o);
    if ((t & 31) == 0) wsum[t >> 5] = acc;
    __syncthreads();
    if (t == 0) {
        float v = 0.f;
        #pragma unroll
        for (int w = 0; w < TPB / 32; w++) v += wsum[w];
        g_pcls[b * GXI + bx] = v;
    }
}

// ============ kernel C: finalize (runs after join) ==========================
__global__ void __launch_bounds__(TPB) final_kernel(
    const float* __restrict__ ann, float* __restrict__ out, int out_size)
{
    __shared__ float s_c[Bn], s_r[Bn];
    const int t = threadIdx.x;
    const int w = t >> 5;                // warp w handles image w
    const int lane = t & 31;

    float C = 0.f, R = 0.f, N = 0.f;
    for (int j = lane; j < GXI; j += 32) C += g_pcls[w * GXI + j];
    for (int j = lane; j < AGX2; j += 32) {
        C += g_pcor[w * AGX2 + j];
        R += g_preg[w * AGX2 + j];
        N += g_pnp [w * AGX2 + j];
    }
    #pragma unroll
    for (int o = 16; o > 0; o >>= 1) {
        C += __shfl_down_sync(0xffffffffu, C, o);
        R += __shfl_down_sync(0xffffffffu, R, o);
        N += __shfl_down_sync(0xffffffffu, N, o);
    }
    float lab = ann[((size_t)w * Mn + lane) * 5 + 4];
    unsigned hasmask = __ballot_sync(0xffffffffu, lab != -1.0f);
    if (lane == 0) {
        float Ct = C + C0_PER_IMAGE;
        float clsv = Ct / fmaxf(N, 0.01f);
        float regv = (N > 0.f) ? (R / fmaxf(N * 4.0f, 1.0f)) : 0.f;
        if (hasmask == 0u) { clsv = 0.f; regv = 0.f; }
        s_c[w] = clsv; s_r[w] = regv;
    }
    __syncthreads();
    if (t == 0) {
        float sc = 0.f, sr = 0.f;
        #pragma unroll
        for (int i = 0; i < Bn; i++) { sc += s_c[i]; sr += s_r[i]; }
        out[0] = sc * (1.0f / (float)Bn);
        if (out_size > 1) out[1] = sr * (1.0f / (float)Bn);
    }
}

// ---------------- launch: fork/join with FOCAL dispatched first --------------
extern "C" void kernel_launch(void* const* d_in, const int* in_sizes, int n_in,
                              void* d_out, int out_size) {
    const float *cls = nullptr, *reg = nullptr, *anc = nullptr, *ann = nullptr;
    for (int i = 0; i < n_in; i++) {
        long long sz = in_sizes[i];
        if      (sz == (long long)Bn * An * Kn) cls = (const float*)d_in[i];
        else if (sz == (long long)Bn * An * 4)  reg = (const float*)d_in[i];
        else if (sz == (long long)An * 4)       anc = (const float*)d_in[i];
        else if (sz == (long long)Bn * Mn * 5)  ann = (const float*)d_in[i];
    }

    // Created once on the FIRST call (the uncaptured correctness run).
    // No device-memory allocation: streams/events only.
    static cudaStream_t s1 = nullptr;
    static cudaEvent_t e_fork = nullptr, e_join = nullptr;
    if (s1 == nullptr) {
        cudaFuncSetAttribute(focal_kernel,
            cudaFuncAttributeMaxDynamicSharedMemorySize, NST * CHUNK_BYTES);
        int pr_least = 0, pr_greatest = 0;
        cudaDeviceGetStreamPriorityRange(&pr_least, &pr_greatest);
        // pr_least = numerically-largest value = LOWEST priority -> assign
        cudaStreamCreateWithPriority(&s1, cudaStreamNonBlocking, pr_least);
        cudaEventCreateWithFlags(&e_fork, cudaEventDisableTiming);
        cudaEventCreateWithFlags(&e_join, cudaEventDisableTiming);
    }

    // fork point (before focal so the assign branch is independent of it)
    cudaEventRecord(e_fork, 0);
    cudaStreamWaitEvent(s1, e_fork, 0);

    // FOCAL FIRST: its node precedes assign's in creation order, so its 440
    // blocks get dispatched before assign's 1568 can fill the SMs.
    dim3 gf(GXI, Bn);
    focal_kernel<<<gf, TPB, NST * CHUNK_BYTES>>>(cls);

    // assign trickles into residual SM capacity on the low-priority stream
    dim3 ga(AGX2, Bn);
    assign_kernel<<<ga, TPB, 0, s1>>>(cls, reg, anc, ann);

    // join: finalize depends on both branches
    cudaEventRecord(e_join, s1);
    cudaStreamWaitEvent(0, e_join, 0);

    final_kernel<<<1, TPB>>>(ann, (float*)d_out, out_size);
}

// round 15
// speedup vs baseline: 1.0770x; 1.0152x over previous
#include <cuda_runtime.h>
#include <math.h>
#include <stdint.h>

#define Bn 8
#define An 100000
#define Kn 80
#define Mn 32
#define F4_TOTAL 2000000                 /* float4 per image */
#define TPB 256

/* ---- assign geometry: 512 anchors per block, 2 per thread (R11) ---- */
#define APB 512
#define AGX2 ((An + APB - 1) / APB)      /* 196 */

/* ---- focal geometry: EXACT R14 config (measured 43.2 us, 76% DRAM) ---- */
#define CHUNK_F4   1024
#define CHUNK_BYTES 16384
#define NST 4                            /* 64 KB dynamic smem */
#define CH_IMG 1954                      /* 1953 full + 1 tail chunk */
#define TAIL_F4 128
#define GXI 55                           /* 440 blocks = 3/SM */
#define NBLKF (GXI * Bn)

typedef unsigned long long u64;

// ---------------- device scratch --------------------------------------------
__device__ float g_pcls[NBLKF];
__device__ float g_preg[Bn * AGX2];
__device__ float g_pnp [Bn * AGX2];
__device__ float g_pcor[Bn * AGX2];

// ---------------- fast intrinsics -------------------------------------------
__device__ __forceinline__ float fast_ex2(float x) { float r; asm("ex2.approx.f32 %0, %1;" : "=f"(r) : "f"(x)); return r; }
__device__ __forceinline__ float fast_lg2(float x) { float r; asm("lg2.approx.f32 %0, %1;" : "=f"(r) : "f"(x)); return r; }
__device__ __forceinline__ float fast_rcp(float x) { float r; asm("rcp.approx.f32 %0, %1;" : "=f"(r) : "f"(x)); return r; }

// ---------------- packed f32x2 helpers --------------------------------------
__device__ __forceinline__ u64 fma2(u64 a, u64 b, u64 c) {
    u64 d; asm("fma.rn.f32x2 %0, %1, %2, %3;" : "=l"(d) : "l"(a), "l"(b), "l"(c)); return d;
}
__device__ __forceinline__ u64 add2(u64 a, u64 b) {
    u64 d; asm("add.rn.f32x2 %0, %1, %2;" : "=l"(d) : "l"(a), "l"(b)); return d;
}
__device__ __forceinline__ void upkf(u64 v, float& lo, float& hi) {
    unsigned a, b; asm("mov.b64 {%0, %1}, %2;" : "=r"(a), "=r"(b) : "l"(v));
    lo = __uint_as_float(a); hi = __uint_as_float(b);
}
__device__ __forceinline__ u64 pk2c(float c) {
    unsigned u = __float_as_uint(c); return ((u64)u << 32) | (u64)u;
}

// ---- degree-6 Taylor of f1(x)=0.25*(1-sigmoid(x))^2*softplus(-x) at x0=0.5
// (validated rounds 4-14 end-to-end at rel_err ~1.36e-6)
#define CB0  0.01689337f
#define CB1 -0.03448426f
#define CB2  0.03005625f
#define CB3 -0.01298390f
#define CB4  0.00148816f
#define CB5  0.00118042f
#define CB6 -0.00048818f
#define C0_PER_IMAGE (CB0 * 8000000.0f)

__device__ __forceinline__ float poly_x(float x) {
    float s = x - 0.5f;
    float p = fmaf(CB6, s, CB5);
    p = fmaf(p, s, CB4); p = fmaf(p, s, CB3);
    p = fmaf(p, s, CB2); p = fmaf(p, s, CB1);
    return fmaf(p, s, CB0);
}
__device__ __forceinline__ float f1_precise(float xc) {
    float e = fast_ex2(-1.44269504f * xc);
    float q = 1.0f + e;
    float u = fast_rcp(q);
    float omp = e * u;
    return 0.17328680f * (omp * omp) * fast_lg2(q);
}
__device__ __forceinline__ float f2_precise(float xc) {
    float e = fast_ex2(-1.44269504f * xc);
    float q = 1.0f + e;
    float u = fast_rcp(q);
    float sp = 0.69314718f * fast_lg2(q);
    return 0.75f * (u * u) * (xc + sp);
}

struct PK { u64 h, c6, c5, c4, c3, c2, c1; };
__device__ __forceinline__ void pair_acc(u64& acc, u64 x2, const PK& K) {
    u64 s = add2(x2, K.h);
    u64 p = fma2(K.c6, s, K.c5);
    p = fma2(p, s, K.c4);
    p = fma2(p, s, K.c3);
    p = fma2(p, s, K.c2);
    p = fma2(p, s, K.c1);
    acc = fma2(p, s, acc);
}

__device__ __forceinline__ void mb_wait_acq(unsigned mb, unsigned ph) {
    asm volatile(
        "{\n\t.reg .pred P1;\n\t"
        "WLP_%=:\n\t"
        "mbarrier.try_wait.parity.acquire.cta.shared::cta.b64 P1, [%0], %1, 0x989680;\n\t"
        "@P1 bra.uni WDN_%=;\n\t"
        "bra.uni WLP_%=;\n\t"
        "WDN_%=:\n\t}"
        :: "r"(mb), "r"(ph) : "memory");
}

// ============ kernel A: assign (byte-identical logic to R11/R14) ============
__global__ void __launch_bounds__(TPB) assign_kernel(
    const float* __restrict__ cls,
    const float* __restrict__ regs,
    const float* __restrict__ anc,
    const float* __restrict__ ann)
{
    __shared__ float4 vbox[Mn];
    __shared__ float  vlab[Mn];
    __shared__ int    s_V;
    __shared__ int    s_pa[APB];
    __shared__ int    s_pcode[APB];
    __shared__ int    s_pcnt;
    __shared__ float  s_regsum;
    __shared__ float  wC[TPB / 32];

    const int b = blockIdx.y;
    const int t = threadIdx.x;

    if (t == 0) { s_pcnt = 0; s_regsum = 0.f; }
    if (t < 32) {
        const float* a5 = ann + ((size_t)b * Mn + t) * 5;
        float x1 = a5[0], y1 = a5[1], x2 = a5[2], y2 = a5[3], lb = a5[4];
        bool val = (lb != -1.0f);
        unsigned m = __ballot_sync(0xffffffffu, val);
        int pos = __popc(m & ((1u << t) - 1));
        int V = __popc(m);
        if (val) {
            vbox[pos] = make_float4(x1, y1, x2, y2);
            vlab[pos] = lb;
        }
        if (t >= V) {
            vbox[t] = make_float4(1e18f, 1e18f, 1e18f, 1e18f);
            vlab[t] = 0.f;
        }
        if (t == 0) s_V = V;
    }
    __syncthreads();
    const int V = s_V;

    const int base = blockIdx.x * APB;
    const int a0 = base + t;
    const int a1 = base + t + TPB;
    const bool ok0 = (a0 < An), ok1 = (a1 < An);
    float4 A0 = ok0 ? *(const float4*)(anc + (size_t)a0 * 4)
                    : make_float4(-1e18f, -1e18f, -1e18f, -1e18f);
    float4 A1 = ok1 ? *(const float4*)(anc + (size_t)a1 * 4)
                    : make_float4(-1e18f, -1e18f, -1e18f, -1e18f);
    const float areaA0 = (A0.z - A0.x) * (A0.w - A0.y);
    const float areaA1 = (A1.z - A1.x) * (A1.w - A1.y);

    bool p0 = false, p1 = false;
    #pragma unroll
    for (int m = 0; m < Mn; m++) {
        float4 bb = vbox[m];
        float barea = (bb.z - bb.x) * (bb.w - bb.y);
        {
            float iw = fmaxf(fminf(A0.z, bb.z) - fmaxf(A0.x, bb.x), 0.f);
            float ih = fmaxf(fminf(A0.w, bb.w) - fmaxf(A0.y, bb.y), 0.f);
            float inter = iw * ih;
            float ua = fmaxf(areaA0 + barea - inter, 1e-8f);
            p0 = p0 || (inter + inter >= ua);
        }
        {
            float iw = fmaxf(fminf(A1.z, bb.z) - fmaxf(A1.x, bb.x), 0.f);
            float ih = fmaxf(fminf(A1.w, bb.w) - fmaxf(A1.y, bb.y), 0.f);
            float inter = iw * ih;
            float ua = fmaxf(areaA1 + barea - inter, 1e-8f);
            p1 = p1 || (inter + inter >= ua);
        }
    }
    if (p0 && ok0) { int i = atomicAdd(&s_pcnt, 1); s_pa[i] = a0; }
    if (p1 && ok1) { int i = atomicAdd(&s_pcnt, 1); s_pa[i] = a1; }
    __syncthreads();
    const int P = s_pcnt;

    for (int i = t; i < P; i += TPB) {
        int ap = s_pa[i];
        float4 av = *(const float4*)(anc + (size_t)ap * 4);
        float px1 = av.x, py1 = av.y, px2 = av.z, py2 = av.w;
        float areaP = (px2 - px1) * (py2 - py1);
        float binter = 0.f, bua = 1.f; int bi = 0;
        for (int m = 0; m < V; m++) {
            float4 bb = vbox[m];
            float barea = (bb.z - bb.x) * (bb.w - bb.y);
            float iw = fmaxf(fminf(px2, bb.z) - fmaxf(px1, bb.x), 0.f);
            float ih = fmaxf(fminf(py2, bb.w) - fmaxf(py1, bb.y), 0.f);
            float inter = iw * ih;
            float ua = fmaxf(areaP + barea - inter, 1e-8f);
            if (m == 0) { binter = inter; bua = ua; }
            else if (inter * bua > binter * ua) { binter = inter; bua = ua; bi = m; }
        }
        s_pcode[i] = (int)vlab[bi];

        float aw = px2 - px1, ah = py2 - py1;
        float acx = px1 + 0.5f * aw, acy = py1 + 0.5f * ah;
        float4 gb = vbox[bi];
        float gw = gb.z - gb.x, gh = gb.w - gb.y;
        float gcx = gb.x + 0.5f * gw, gcy = gb.y + 0.5f * gh;
        gw = fmaxf(gw, 1.0f); gh = fmaxf(gh, 1.0f);
        float tt0 = ((gcx - acx) / aw) / 0.1f;
        float tt1 = ((gcy - acy) / ah) / 0.1f;
        float tt2 = __logf(gw / aw) / 0.2f;
        float tt3 = __logf(gh / ah) / 0.2f;
        float4 rv = *(const float4*)(regs + ((size_t)b * An + ap) * 4);
        float d0 = fabsf(tt0 - rv.x), d1 = fabsf(tt1 - rv.y);
        float d2 = fabsf(tt2 - rv.z), d3 = fabsf(tt3 - rv.w);
        float srl = 0.f;
        srl += (d0 <= (float)(1.0/9.0)) ? 4.5f*d0*d0 : d0 - (float)(0.5/9.0);
        srl += (d1 <= (float)(1.0/9.0)) ? 4.5f*d1*d1 : d1 - (float)(0.5/9.0);
        srl += (d2 <= (float)(1.0/9.0)) ? 4.5f*d2*d2 : d2 - (float)(0.5/9.0);
        srl += (d3 <= (float)(1.0/9.0)) ? 4.5f*d3*d3 : d3 - (float)(0.5/9.0);
        atomicAdd(&s_regsum, srl);
    }
    __syncthreads();

    float corr = 0.f;
    const int total = P * 20;
    for (int w = t; w < total; w += TPB) {
        int i = w / 20, j = w - i * 20;
        int ap = s_pa[i];
        int code = s_pcode[i];
        float4 c = *((const float4*)(cls + ((size_t)b * An + ap) * Kn) + j);
        int k0 = j * 4;
        #pragma unroll
        for (int e = 0; e < 4; e++) {
            float x = (e == 0) ? c.x : (e == 1) ? c.y : (e == 2) ? c.z : c.w;
            float xc = fminf(fmaxf(x, 1e-4f), 0.9999f);
            float truth = (k0 + e == code) ? f1_precise(xc) : f2_precise(xc);
            corr += truth - poly_x(x);
        }
    }
    #pragma unroll
    for (int o = 16; o > 0; o >>= 1) corr += __shfl_down_sync(0xffffffffu, corr, o);
    if ((t & 31) == 0) wC[t >> 5] = corr;
    __syncthreads();
    if (t == 0) {
        float C = 0.f;
        #pragma unroll
        for (int w2 = 0; w2 < TPB / 32; w2++) C += wC[w2];
        int bid = b * AGX2 + blockIdx.x;
        g_pnp [bid] = (float)P;
        g_preg[bid] = s_regsum;
        g_pcor[bid] = C;
    }
}

// ============ kernel B: R14 TMA streaming poly (43.2us, 76% DRAM) ===========
__global__ void __launch_bounds__(TPB) focal_kernel(const float* __restrict__ cls)
{
    extern __shared__ char dynsmem[];            // NST * CHUNK_BYTES = 64 KB
    __shared__ u64 mbar[NST];
    __shared__ float wsum[TPB / 32];

    const int b  = blockIdx.y;
    const int bx = blockIdx.x;
    const int t  = threadIdx.x;

    const unsigned smem_base = (unsigned)__cvta_generic_to_shared(dynsmem);
    const unsigned mbar_base = (unsigned)__cvta_generic_to_shared(&mbar[0]);
    const char* gbase = (const char*)cls + (size_t)b * F4_TOTAL * 16;

    if (t == 0) {
        #pragma unroll
        for (int s = 0; s < NST; s++)
            asm volatile("mbarrier.init.shared.b64 [%0], %1;"
                         :: "r"(mbar_base + s * 8), "r"(1u) : "memory");
    }
    __syncthreads();

    const int n = (CH_IMG - bx + GXI - 1) / GXI;

    auto issue = [&](int i) {
        int c = bx + i * GXI;
        unsigned cnt = (c == CH_IMG - 1) ? TAIL_F4 : CHUNK_F4;
        unsigned bytes = cnt * 16u;
        int st = i & (NST - 1);
        unsigned mb = mbar_base + st * 8;
        asm volatile("mbarrier.arrive.expect_tx.shared.b64 _, [%0], %1;"
                     :: "r"(mb), "r"(bytes) : "memory");
        asm volatile("cp.async.bulk.shared::cta.global.mbarrier::complete_tx::bytes [%0], [%1], %2, [%3];"
                     :: "r"(smem_base + st * CHUNK_BYTES),
                        "l"(gbase + (size_t)c * CHUNK_BYTES),
                        "r"(bytes), "r"(mb) : "memory");
    };

    if (t == 0) {
        for (int i = 0; i < n && i < NST; i++) issue(i);
    }

    PK K;
    K.h  = pk2c(-0.5f);
    K.c6 = pk2c(CB6); K.c5 = pk2c(CB5); K.c4 = pk2c(CB4);
    K.c3 = pk2c(CB3); K.c2 = pk2c(CB2); K.c1 = pk2c(CB1);

    u64 accA = 0ull, accB = 0ull;

    for (int i = 0; i < n; i++) {
        int st = i & (NST - 1);
        unsigned ph = (unsigned)((i >> 2) & 1);
        mb_wait_acq(mbar_base + st * 8, ph);

        int c = bx + i * GXI;
        const ulonglong2* sp = (const ulonglong2*)(dynsmem + st * CHUNK_BYTES);
        if (c != CH_IMG - 1) {
            ulonglong2 v0 = sp[t];
            ulonglong2 v1 = sp[t + 256];
            ulonglong2 v2 = sp[t + 512];
            ulonglong2 v3 = sp[t + 768];
            pair_acc(accA, v0.x, K); pair_acc(accB, v0.y, K);
            pair_acc(accA, v1.x, K); pair_acc(accB, v1.y, K);
            pair_acc(accA, v2.x, K); pair_acc(accB, v2.y, K);
            pair_acc(accA, v3.x, K); pair_acc(accB, v3.y, K);
        } else {
            if (t < TAIL_F4) {
                ulonglong2 v = sp[t];
                pair_acc(accA, v.x, K); pair_acc(accB, v.y, K);
            }
        }
        __syncthreads();
        if (t == 0 && i + NST < n) issue(i + NST);
    }

    float la, ha, lb2, hb2;
    upkf(accA, la, ha); upkf(accB, lb2, hb2);
    float acc = (la + ha) + (lb2 + hb2);

    #pragma unroll
    for (int o = 16; o > 0; o >>= 1) acc += __shfl_down_sync(0xffffffffu, acc, o);
    if ((t & 31) == 0) wsum[t >> 5] = acc;
    __syncthreads();
    if (t == 0) {
        float v = 0.f;
        #pragma unroll
        for (int w = 0; w < TPB / 32; w++) v += wsum[w];
        g_pcls[b * GXI + bx] = v;
    }
}

// ============ kernel C: finalize (runs after join) ==========================
__global__ void __launch_bounds__(TPB) final_kernel(
    const float* __restrict__ ann, float* __restrict__ out, int out_size)
{
    __shared__ float s_c[Bn], s_r[Bn];
    const int t = threadIdx.x;
    const int w = t >> 5;                // warp w handles image w
    const int lane = t & 31;

    float C = 0.f, R = 0.f, N = 0.f;
    for (int j = lane; j < GXI; j += 32) C += g_pcls[w * GXI + j];
    for (int j = lane; j < AGX2; j += 32) {
        C += g_pcor[w * AGX2 + j];
        R += g_preg[w * AGX2 + j];
        N += g_pnp [w * AGX2 + j];
    }
    #pragma unroll
    for (int o = 16; o > 0; o >>= 1) {
        C += __shfl_down_sync(0xffffffffu, C, o);
        R += __shfl_down_sync(0xffffffffu, R, o);
        N += __shfl_down_sync(0xffffffffu, N, o);
    }
    float lab = ann[((size_t)w * Mn + lane) * 5 + 4];
    unsigned hasmask = __ballot_sync(0xffffffffu, lab != -1.0f);
    if (lane == 0) {
        float Ct = C + C0_PER_IMAGE;
        float clsv = Ct / fmaxf(N, 0.01f);
        float regv = (N > 0.f) ? (R / fmaxf(N * 4.0f, 1.0f)) : 0.f;
        if (hasmask == 0u) { clsv = 0.f; regv = 0.f; }
        s_c[w] = clsv; s_r[w] = regv;
    }
    __syncthreads();
    if (t == 0) {
        float sc = 0.f, sr = 0.f;
        #pragma unroll
        for (int i = 0; i < Bn; i++) { sc += s_c[i]; sr += s_r[i]; }
        out[0] = sc * (1.0f / (float)Bn);
        if (out_size > 1) out[1] = sr * (1.0f / (float)Bn);
    }
}

// ---------------- launch: fork/join, focal first, EQUAL priority -------------
extern "C" void kernel_launch(void* const* d_in, const int* in_sizes, int n_in,
                              void* d_out, int out_size) {
    const float *cls = nullptr, *reg = nullptr, *anc = nullptr, *ann = nullptr;
    for (int i = 0; i < n_in; i++) {
        long long sz = in_sizes[i];
        if      (sz == (long long)Bn * An * Kn) cls = (const float*)d_in[i];
        else if (sz == (long long)Bn * An * 4)  reg = (const float*)d_in[i];
        else if (sz == (long long)An * 4)       anc = (const float*)d_in[i];
        else if (sz == (long long)Bn * Mn * 5)  ann = (const float*)d_in[i];
    }

    // Created once on the FIRST call (the uncaptured correctness run).
    // No device-memory allocation: streams/events only.
    static cudaStream_t s1 = nullptr;
    static cudaEvent_t e_fork = nullptr, e_join = nullptr;
    if (s1 == nullptr) {
        cudaFuncSetAttribute(focal_kernel,
            cudaFuncAttributeMaxDynamicSharedMemorySize, NST * CHUNK_BYTES);
        // DEFAULT priority: low-priority dispatch deferral was the R14
        // serializer hypothesis; equal priority allows backfill.
        cudaStreamCreateWithFlags(&s1, cudaStreamNonBlocking);
        cudaEventCreateWithFlags(&e_fork, cudaEventDisableTiming);
        cudaEventCreateWithFlags(&e_join, cudaEventDisableTiming);
    }

    // fork point (before focal so the assign branch is independent of it)
    cudaEventRecord(e_fork, 0);
    cudaStreamWaitEvent(s1, e_fork, 0);

    // FOCAL FIRST: node creation order -> its 440 blocks dispatch first.
    dim3 gf(GXI, Bn);
    focal_kernel<<<gf, TPB, NST * CHUNK_BYTES>>>(cls);

    // assign backfills residual SM capacity concurrently (equal priority)
    dim3 ga(AGX2, Bn);
    assign_kernel<<<ga, TPB, 0, s1>>>(cls, reg, anc, ann);

    // join: finalize depends on both branches
    cudaEventRecord(e_join, s1);
    cudaStreamWaitEvent(0, e_join, 0);

    final_kernel<<<1, TPB>>>(ann, (float*)d_out, out_size);
}